// round 16
// baseline (speedup 1.0000x reference)
#include <cuda_runtime.h>
#include <cuda_fp16.h>
#include <cstdint>
#include <math.h>

#define N_TOK 2048
#define DIM   1024
#define NEXP  16
#define HID   2048
#define OUTD  1024
#define TOPK  2
#define NPAIR (N_TOK*TOPK)
#define W1ELEMS (NEXP*HID*DIM)    // 32M
#define W2ELEMS (NEXP*OUTD*HID)   // 32M

// ---------------- scratch ----------------------------------------------------
__device__ int    g_cnt[NEXP];
__device__ int    g_off[NEXP+1];
__device__ int    g_cur[NEXP];
__device__ int    g_tok[NPAIR];
__device__ float  g_prob[NPAIR];
__device__ int    g_tidx[N_TOK*TOPK];
__device__ float  g_tp[N_TOK*TOPK];
__device__ __half g_h16[(size_t)NPAIR*HID];          // 16 MB hidden activations
__device__ __half g_w16[(size_t)W1ELEMS + W2ELEMS];  // 128 MB fp16 weights

// ---------------- helpers -----------------------------------------------------
__device__ __forceinline__ uint32_t smem_u32(const void* p) {
    uint32_t a;
    asm("{ .reg .u64 t; cvta.to.shared.u64 t, %1; cvt.u32.u64 %0, t; }" : "=r"(a) : "l"(p));
    return a;
}

__device__ __forceinline__ uint2 half4(float4 v) {
    __half2 h01 = __floats2half2_rn(v.x, v.y);
    __half2 h23 = __floats2half2_rn(v.z, v.w);
    uint2 r;
    r.x = *reinterpret_cast<uint32_t*>(&h01);
    r.y = *reinterpret_cast<uint32_t*>(&h23);
    return r;
}

__device__ __forceinline__ void mma16816(float* d, const uint32_t* a, const uint32_t* b) {
    asm volatile(
        "mma.sync.aligned.m16n8k16.row.col.f32.f16.f16.f32 "
        "{%0,%1,%2,%3}, {%4,%5,%6,%7}, {%8,%9}, {%0,%1,%2,%3};"
        : "+f"(d[0]), "+f"(d[1]), "+f"(d[2]), "+f"(d[3])
        : "r"(a[0]), "r"(a[1]), "r"(a[2]), "r"(a[3]), "r"(b[0]), "r"(b[1]));
}

__device__ __forceinline__ void ldmx4(uint32_t& r0, uint32_t& r1, uint32_t& r2, uint32_t& r3,
                                      uint32_t addr) {
    asm volatile("ldmatrix.sync.aligned.m8n8.x4.shared.b16 {%0,%1,%2,%3}, [%4];"
                 : "=r"(r0), "=r"(r1), "=r"(r2), "=r"(r3) : "r"(addr));
}

__device__ __forceinline__ void cpasync16(uint32_t dst, const void* src) {
    asm volatile("cp.async.cg.shared.global [%0], [%1], 16;"
                 :: "r"(dst), "l"(src) : "memory");
}
#define CP_COMMIT()  asm volatile("cp.async.commit_group;" ::: "memory")
#define CP_WAIT(N)   asm volatile("cp.async.wait_group %0;" :: "n"(N) : "memory")

// ---------------- small kernels ----------------------------------------------
__global__ void init_kernel() {
    if (threadIdx.x < NEXP) g_cnt[threadIdx.x] = 0;
}

// fp32 weights -> fp16 (8 elems/thread)
__global__ void convert_w_kernel(const float* __restrict__ w1,
                                 const float* __restrict__ w2) {
    size_t i = ((size_t)blockIdx.x * blockDim.x + threadIdx.x) * 8;
    const float* src; size_t off = i;
    if (i < (size_t)W1ELEMS) { src = w1; }
    else                     { src = w2; off = i - W1ELEMS; }
    float4 a = *(const float4*)(src + off);
    float4 b = *(const float4*)(src + off + 4);
    uint2 ha = half4(a), hb = half4(b);
    *(uint4*)&g_w16[i] = make_uint4(ha.x, ha.y, hb.x, hb.y);
}

__global__ void router_kernel(const float* __restrict__ z,
                              const float* __restrict__ rw,
                              const float* __restrict__ rb) {
    int n    = blockIdx.x;
    int tid  = threadIdx.x;
    int warp = tid >> 5, lane = tid & 31;
    __shared__ float logits[NEXP];
    const float* zr = z + (size_t)n * DIM;
    for (int e = warp; e < NEXP; e += 4) {
        const float* wr = rw + (size_t)e * DIM;
        float s = 0.f;
        for (int d = lane; d < DIM; d += 32) s += zr[d] * wr[d];
        #pragma unroll
        for (int o = 16; o; o >>= 1) s += __shfl_xor_sync(0xffffffffu, s, o);
        if (lane == 0) logits[e] = s + rb[e];
    }
    __syncthreads();
    if (tid == 0) {
        int i0 = 0; float v0 = logits[0];
        for (int e = 1; e < NEXP; e++) if (logits[e] > v0) { v0 = logits[e]; i0 = e; }
        int i1 = -1; float v1 = -1e30f;
        for (int e = 0; e < NEXP; e++) if (e != i0 && logits[e] > v1) { v1 = logits[e]; i1 = e; }
        float e2 = expf(v1 - v0);
        float inv = 1.0f / (1.0f + e2);
        g_tidx[n*2+0] = i0; g_tidx[n*2+1] = i1;
        g_tp[n*2+0] = inv;  g_tp[n*2+1] = e2 * inv;
        atomicAdd(&g_cnt[i0], 1);
        atomicAdd(&g_cnt[i1], 1);
    }
}

__global__ void scan_kernel() {
    if (threadIdx.x == 0) {
        int acc = 0;
        for (int e = 0; e < NEXP; e++) { g_off[e] = acc; g_cur[e] = acc; acc += g_cnt[e]; }
        g_off[NEXP] = acc;
    }
}

__global__ void scatter_kernel() {
    int n = blockIdx.x * blockDim.x + threadIdx.x;
    if (n >= N_TOK) return;
    #pragma unroll
    for (int k = 0; k < TOPK; k++) {
        int e = g_tidx[n*2+k];
        int pos = atomicAdd(&g_cur[e], 1);
        g_tok[pos]  = n;
        g_prob[pos] = g_tp[n*2+k];
    }
}

// ---------------- grouped GEMM: fp16, cp.async 3-stage, 512 thr, 128x256 ------
// 16 warps, 2(M) x 8(N); warp tile 64x32 (4 m-frags x 4 n-frags), m16n8k16.
#define KC 32
#define SA 40                    // fp16 elems per smem row (80 B)
#define ABUF (128 * SA)
#define BBUF (256 * SA)
#define NSTG 3
#define SMEM_BYTES (NSTG * (ABUF + BBUF) * 2)   // 92160 B

// MODE 0: A = z[g_tok[pos]] (fp32 -> reg conv -> STS), epilogue bias+gelu -> g_h16
// MODE 1: A = g_h16[pos] (fp16 cp.async),  epilogue prob*(acc+bias) atomicAdd -> out
template<int KDIM, int NDIM, int MODE>
__global__ __launch_bounds__(512, 1)
void moe_gemm(const float* __restrict__ Az, const __half* __restrict__ Bw16,
              const float* __restrict__ bias, float* __restrict__ outp)
{
    constexpr int NC = KDIM / KC;
    int e   = blockIdx.z;
    int cnt = g_cnt[e];
    int m0  = blockIdx.y * 128;
    if (m0 >= cnt) return;
    int off = g_off[e];
    int n0  = blockIdx.x * 256;
    int cntRem = cnt - m0;

    extern __shared__ __align__(16) uint16_t smbuf[];
    uint16_t* Ah = smbuf;                  // [NSTG][ABUF]
    uint16_t* Bh = smbuf + NSTG * ABUF;    // [NSTG][BBUF]
    uint32_t AhA = smem_u32(Ah);
    uint32_t BhA = smem_u32(Bh);

    int tid  = threadIdx.x;
    int wid  = tid >> 5, lane = tid & 31;
    int wm   = wid >> 3, wn = wid & 7;          // 2 x 8 warp grid
    int quad = lane >> 2, tq = lane & 3;

    // ldmatrix per-lane bases
    int a_row  = wm*64 + (lane & 15);
    int a_koff = (lane >> 4) * 8;
    int b_row  = wn*32 + (lane & 7) + ((lane >> 4) & 1) * 8;
    int b_koff = ((lane >> 3) & 1) * 8;

    // B staging: 2 threads per row, 2x16B each
    int brow_s = tid >> 1, bseg = tid & 1;
    const __half* bsrc = Bw16 + ((size_t)e * NDIM + n0 + brow_s) * KDIM + bseg * 16;
    uint32_t bdst_base = BhA + (uint32_t)((brow_s * SA + bseg * 16) * 2);

    // A staging: 4 threads per row, 8 elems (16 B) each
    int arowA = tid >> 2, acolA = (tid & 3) * 8;
    int rclampA = arowA < cntRem ? arowA : (cntRem - 1);
    const float*  arowf = nullptr;
    const __half* arowh = nullptr;
    if (MODE == 0) {
        int tok = g_tok[off + m0 + rclampA];
        arowf = Az + (size_t)tok * KDIM + acolA;
    } else {
        arowh = g_h16 + (size_t)(off + m0 + rclampA) * KDIM + acolA;
    }
    uint32_t adst_base = AhA + (uint32_t)((arowA * SA + acolA) * 2);

    float acc[4][4][4];
    #pragma unroll
    for (int i = 0; i < 4; i++)
        #pragma unroll
        for (int j = 0; j < 4; j++)
            #pragma unroll
            for (int q = 0; q < 4; q++) acc[i][j][q] = 0.f;

    float4 pa0, pa1;                      // MODE 0 A reg pipeline
    if (MODE == 0) {
        pa0 = *(const float4*)(arowf);
        pa1 = *(const float4*)(arowf + 4);
    }

    // stage chunk c into buffer c%NSTG
    auto stageB = [&](int c) {
        uint32_t d = bdst_base + (uint32_t)((c % NSTG) * BBUF * 2);
        const __half* s = bsrc + c * KC;
        cpasync16(d,      s);
        cpasync16(d + 16, s + 8);
    };
    auto stageA = [&](int c) {
        uint32_t d = adst_base + (uint32_t)((c % NSTG) * ABUF * 2);
        if (MODE == 1) {
            cpasync16(d, arowh + c * KC);
        } else {
            uint2 h0 = half4(pa0), h1 = half4(pa1);
            *(uint4*)((char*)smbuf + (d - smem_u32(smbuf))) = make_uint4(h0.x, h0.y, h1.x, h1.y);
            if (c + 1 < NC) {
                pa0 = *(const float4*)(arowf + (c+1)*KC);
                pa1 = *(const float4*)(arowf + (c+1)*KC + 4);
            }
        }
    };

    stageB(0); stageA(0); CP_COMMIT();
    stageB(1); stageA(1); CP_COMMIT();

    for (int ch = 0; ch < NC; ch++) {
        if (ch + 1 < NC) { CP_WAIT(1); } else { CP_WAIT(0); }
        __syncthreads();
        if (ch + 2 < NC) { stageB(ch + 2); stageA(ch + 2); CP_COMMIT(); }

        int s = ch % NSTG;
        uint32_t bbA = (uint32_t)(s * ABUF * 2);
        uint32_t bbB = (uint32_t)(s * BBUF * 2);
        #pragma unroll
        for (int ks = 0; ks < 2; ks++) {
            int kb = ks * 16;
            uint32_t bH[4][2];
            #pragma unroll
            for (int p = 0; p < 2; p++) {
                uint32_t boffB = bbB + (uint32_t)(((b_row + p*16) * SA + kb + b_koff) * 2);
                ldmx4(bH[2*p][0], bH[2*p][1], bH[2*p+1][0], bH[2*p+1][1], BhA + boffB);
            }
            #pragma unroll
            for (int fi = 0; fi < 4; fi++) {
                uint32_t aoff = bbA + (uint32_t)(((a_row + fi*16) * SA + kb + a_koff) * 2);
                uint32_t aH[4];
                ldmx4(aH[0], aH[1], aH[2], aH[3], AhA + aoff);
                #pragma unroll
                for (int nj = 0; nj < 4; nj++) mma16816(acc[fi][nj], aH, bH[nj]);
            }
        }
    }

    // ---------------- epilogue ----------------
    #pragma unroll
    for (int fi = 0; fi < 4; fi++) {
        #pragma unroll
        for (int half = 0; half < 2; half++) {
            int rr = wm*64 + fi*16 + quad + half*8;
            if (rr >= cntRem) continue;
            int pos = off + m0 + rr;
            if (MODE == 0) {
                __half* dst = g_h16 + (size_t)pos * NDIM + n0;
                const float* bp = bias + (size_t)e * NDIM + n0;
                #pragma unroll
                for (int nj = 0; nj < 4; nj++) {
                    int col = wn*32 + nj*8 + tq*2;
                    float x0 = acc[fi][nj][half*2+0] + bp[col];
                    float x1 = acc[fi][nj][half*2+1] + bp[col+1];
                    float g0 = 0.5f * x0 * (1.0f + erff(x0 * 0.70710678118654752f));
                    float g1 = 0.5f * x1 * (1.0f + erff(x1 * 0.70710678118654752f));
                    __half2 o = __floats2half2_rn(g0, g1);
                    *(uint32_t*)(dst + col) = *reinterpret_cast<uint32_t*>(&o);
                }
            } else {
                int   tok = g_tok[pos];
                float p   = g_prob[pos];
                float* dst = outp + (size_t)tok * NDIM + n0;
                const float* bp = bias + (size_t)e * NDIM + n0;
                #pragma unroll
                for (int nj = 0; nj < 4; nj++) {
                    int col = wn*32 + nj*8 + tq*2;
                    atomicAdd(dst + col,     p * (acc[fi][nj][half*2+0] + bp[col]));
                    atomicAdd(dst + col + 1, p * (acc[fi][nj][half*2+1] + bp[col+1]));
                }
            }
        }
    }
}

// ---------------- launch ------------------------------------------------------
extern "C" void kernel_launch(void* const* d_in, const int* in_sizes, int n_in,
                              void* d_out, int out_size) {
    const float* z  = (const float*)d_in[0];
    const float* rw = (const float*)d_in[1];
    const float* rb = (const float*)d_in[2];
    const float* w1 = (const float*)d_in[3];
    const float* b1 = (const float*)d_in[4];
    const float* w2 = (const float*)d_in[5];
    const float* b2 = (const float*)d_in[6];
    float* out = (float*)d_out;

    cudaFuncSetAttribute(moe_gemm<DIM, HID, 0>,
                         cudaFuncAttributeMaxDynamicSharedMemorySize, SMEM_BYTES);
    cudaFuncSetAttribute(moe_gemm<HID, OUTD, 1>,
                         cudaFuncAttributeMaxDynamicSharedMemorySize, SMEM_BYTES);

    init_kernel<<<1, 32>>>();
    convert_w_kernel<<<(W1ELEMS + W2ELEMS) / (256 * 8), 256>>>(w1, w2);
    router_kernel<<<N_TOK, 128>>>(z, rw, rb);
    scan_kernel<<<1, 32>>>();
    scatter_kernel<<<(N_TOK + 255) / 256, 256>>>();
    cudaMemsetAsync(out, 0, (size_t)N_TOK * OUTD * sizeof(float), 0);

    __half* w16_base = nullptr;
    cudaGetSymbolAddress((void**)&w16_base, g_w16);

    dim3 g1(HID / 256, (NPAIR + 127) / 128, NEXP);
    moe_gemm<DIM, HID, 0><<<g1, 512, SMEM_BYTES>>>(z, w16_base, b1, nullptr);
    dim3 g2(OUTD / 256, (NPAIR + 127) / 128, NEXP);
    moe_gemm<HID, OUTD, 1><<<g2, 512, SMEM_BYTES>>>(nullptr, w16_base + W1ELEMS, b2, out);
}

// round 17
// speedup vs baseline: 1.0956x; 1.0956x over previous
#include <cuda_runtime.h>
#include <cuda_fp16.h>
#include <cstdint>
#include <math.h>

#define N_TOK 2048
#define DIM   1024
#define NEXP  16
#define HID   2048
#define OUTD  1024
#define TOPK  2
#define NPAIR (N_TOK*TOPK)
#define W1ELEMS (NEXP*HID*DIM)    // 33.5M
#define W2ELEMS (NEXP*OUTD*HID)   // 33.5M
#define CONV1_BLOCKS 1024
#define CONV1_PER_BLK (W1ELEMS / CONV1_BLOCKS)   // 32768

// ---------------- scratch ----------------------------------------------------
__device__ int    g_cnt[NEXP];
__device__ int    g_cur[NEXP];
__device__ int    g_tok[NPAIR];
__device__ float  g_prob[NPAIR];
__device__ int    g_tidx[N_TOK*TOPK];
__device__ float  g_tp[N_TOK*TOPK];
__device__ __half g_h16[(size_t)NPAIR*HID];          // 16 MB hidden activations
__device__ __half g_w16[(size_t)W1ELEMS + W2ELEMS];  // 128 MB fp16 weights

// ---------------- helpers -----------------------------------------------------
__device__ __forceinline__ uint32_t smem_u32(const void* p) {
    uint32_t a;
    asm("{ .reg .u64 t; cvta.to.shared.u64 t, %1; cvt.u32.u64 %0, t; }" : "=r"(a) : "l"(p));
    return a;
}

__device__ __forceinline__ uint2 half4(float4 v) {
    __half2 h01 = __floats2half2_rn(v.x, v.y);
    __half2 h23 = __floats2half2_rn(v.z, v.w);
    uint2 r;
    r.x = *reinterpret_cast<uint32_t*>(&h01);
    r.y = *reinterpret_cast<uint32_t*>(&h23);
    return r;
}

__device__ __forceinline__ void mma16816(float* d, const uint32_t* a, const uint32_t* b) {
    asm volatile(
        "mma.sync.aligned.m16n8k16.row.col.f32.f16.f16.f32 "
        "{%0,%1,%2,%3}, {%4,%5,%6,%7}, {%8,%9}, {%0,%1,%2,%3};"
        : "+f"(d[0]), "+f"(d[1]), "+f"(d[2]), "+f"(d[3])
        : "r"(a[0]), "r"(a[1]), "r"(a[2]), "r"(a[3]), "r"(b[0]), "r"(b[1]));
}

__device__ __forceinline__ void ldmx4(uint32_t& r0, uint32_t& r1, uint32_t& r2, uint32_t& r3,
                                      uint32_t addr) {
    asm volatile("ldmatrix.sync.aligned.m8n8.x4.shared.b16 {%0,%1,%2,%3}, [%4];"
                 : "=r"(r0), "=r"(r1), "=r"(r2), "=r"(r3) : "r"(addr));
}

__device__ __forceinline__ void cpasync16(uint32_t dst, const void* src) {
    asm volatile("cp.async.cg.shared.global [%0], [%1], 16;"
                 :: "r"(dst), "l"(src) : "memory");
}
#define CP_COMMIT()  asm volatile("cp.async.commit_group;" ::: "memory")
#define CP_WAIT(N)   asm volatile("cp.async.wait_group %0;" :: "n"(N) : "memory")

// prefix sum of g_cnt below expert e (16 experts, trivial)
__device__ __forceinline__ int expert_off(int e) {
    int off = 0;
    #pragma unroll
    for (int i = 0; i < NEXP; i++) off += (i < e) ? g_cnt[i] : 0;
    return off;
}

// ---------------- small kernels ----------------------------------------------
__global__ void init_kernel() {
    if (threadIdx.x < NEXP) { g_cnt[threadIdx.x] = 0; g_cur[threadIdx.x] = 0; }
}

// blocks [0, N_TOK): router. blocks [N_TOK, N_TOK+CONV1_BLOCKS): convert w1->fp16.
__global__ void router_conv_kernel(const float* __restrict__ z,
                                   const float* __restrict__ rw,
                                   const float* __restrict__ rb,
                                   const float* __restrict__ w1) {
    int tid  = threadIdx.x;
    if (blockIdx.x >= N_TOK) {
        // ---- convert a 32768-elem slice of w1 ----
        size_t base = (size_t)(blockIdx.x - N_TOK) * CONV1_PER_BLK;
        #pragma unroll 4
        for (int it = 0; it < CONV1_PER_BLK / (128 * 8); it++) {
            size_t i = base + (size_t)it * 1024 + tid * 8;
            float4 a = *(const float4*)(w1 + i);
            float4 b = *(const float4*)(w1 + i + 4);
            uint2 ha = half4(a), hb = half4(b);
            *(uint4*)&g_w16[i] = make_uint4(ha.x, ha.y, hb.x, hb.y);
        }
        return;
    }
    int n    = blockIdx.x;
    int warp = tid >> 5, lane = tid & 31;
    __shared__ float logits[NEXP];
    const float* zr = z + (size_t)n * DIM;
    for (int e = warp; e < NEXP; e += 4) {
        const float* wr = rw + (size_t)e * DIM;
        float s = 0.f;
        for (int d = lane; d < DIM; d += 32) s += zr[d] * wr[d];
        #pragma unroll
        for (int o = 16; o; o >>= 1) s += __shfl_xor_sync(0xffffffffu, s, o);
        if (lane == 0) logits[e] = s + rb[e];
    }
    __syncthreads();
    if (tid == 0) {
        int i0 = 0; float v0 = logits[0];
        for (int e = 1; e < NEXP; e++) if (logits[e] > v0) { v0 = logits[e]; i0 = e; }
        int i1 = -1; float v1 = -1e30f;
        for (int e = 0; e < NEXP; e++) if (e != i0 && logits[e] > v1) { v1 = logits[e]; i1 = e; }
        float e2 = expf(v1 - v0);
        float inv = 1.0f / (1.0f + e2);
        g_tidx[n*2+0] = i0; g_tidx[n*2+1] = i1;
        g_tp[n*2+0] = inv;  g_tp[n*2+1] = e2 * inv;
        atomicAdd(&g_cnt[i0], 1);
        atomicAdd(&g_cnt[i1], 1);
    }
}

// scatter with local prefix-sum (no scan kernel)
__global__ void scatter_kernel() {
    int n = blockIdx.x * blockDim.x + threadIdx.x;
    if (n >= N_TOK) return;
    #pragma unroll
    for (int k = 0; k < TOPK; k++) {
        int e = g_tidx[n*2+k];
        int pos = expert_off(e) + atomicAdd(&g_cur[e], 1);
        g_tok[pos]  = n;
        g_prob[pos] = g_tp[n*2+k];
    }
}

// ---------------- grouped GEMM: fp16, cp.async 4-stage, 512 thr, 128x256 ------
// 16 warps, 2(M) x 8(N); warp tile 64x32 (4 m-frags x 4 n-frags), m16n8k16.
#define KC 32
#define SA 40                    // fp16 elems per smem row (80 B)
#define ABUF (128 * SA)
#define BBUF (256 * SA)
#define NSTG 4
#define SMEM_BYTES (NSTG * (ABUF + BBUF) * 2)   // 122880 B

// MODE 0: A = z[g_tok[pos]] (fp32 -> reg conv -> STS), epilogue bias+gelu -> g_h16
//         blockIdx.z == NEXP -> convert a slice of w2 into g_w16[W1ELEMS..]
// MODE 1: A = g_h16[pos] (fp16 cp.async),  epilogue prob*(acc+bias) atomicAdd -> out
template<int KDIM, int NDIM, int MODE>
__global__ __launch_bounds__(512, 1)
void moe_gemm(const float* __restrict__ Az, const __half* __restrict__ Bw16,
              const float* __restrict__ bias, float* __restrict__ outp,
              const float* __restrict__ w2src)
{
    constexpr int NC = KDIM / KC;
    int tid  = threadIdx.x;
    if (MODE == 0 && blockIdx.z == NEXP) {
        // ---- convert a slice of w2 (256 blocks x 131072 elems) ----
        int cb = blockIdx.y * gridDim.x + blockIdx.x;     // 0..255
        size_t base = (size_t)cb * (W2ELEMS / 256);
        #pragma unroll 4
        for (int it = 0; it < (W2ELEMS / 256) / (512 * 8); it++) {
            size_t i = base + (size_t)it * 4096 + tid * 8;
            float4 a = *(const float4*)(w2src + i);
            float4 b = *(const float4*)(w2src + i + 4);
            uint2 ha = half4(a), hb = half4(b);
            *(uint4*)&g_w16[(size_t)W1ELEMS + i] = make_uint4(ha.x, ha.y, hb.x, hb.y);
        }
        return;
    }
    int e   = blockIdx.z;
    int cnt = g_cnt[e];
    int m0  = blockIdx.y * 128;
    if (m0 >= cnt) return;
    int off = expert_off(e);
    int n0  = blockIdx.x * 256;
    int cntRem = cnt - m0;

    extern __shared__ __align__(16) uint16_t smbuf[];
    uint16_t* Ah = smbuf;                  // [NSTG][ABUF]
    uint16_t* Bh = smbuf + NSTG * ABUF;    // [NSTG][BBUF]
    uint32_t AhA = smem_u32(Ah);
    uint32_t BhA = smem_u32(Bh);

    int wid  = tid >> 5, lane = tid & 31;
    int wm   = wid >> 3, wn = wid & 7;          // 2 x 8 warp grid
    int quad = lane >> 2, tq = lane & 3;

    // ldmatrix per-lane bases
    int a_row  = wm*64 + (lane & 15);
    int a_koff = (lane >> 4) * 8;
    int b_row  = wn*32 + (lane & 7) + ((lane >> 4) & 1) * 8;
    int b_koff = ((lane >> 3) & 1) * 8;

    // B staging: 2 threads per row, 2x16B each
    int brow_s = tid >> 1, bseg = tid & 1;
    const __half* bsrc = Bw16 + ((size_t)e * NDIM + n0 + brow_s) * KDIM + bseg * 16;
    uint32_t bdst_base = BhA + (uint32_t)((brow_s * SA + bseg * 16) * 2);

    // A staging: 4 threads per row, 8 elems (16 B) each
    int arowA = tid >> 2, acolA = (tid & 3) * 8;
    int rclampA = arowA < cntRem ? arowA : (cntRem - 1);
    const float*  arowf = nullptr;
    const __half* arowh = nullptr;
    if (MODE == 0) {
        int tok = g_tok[off + m0 + rclampA];
        arowf = Az + (size_t)tok * KDIM + acolA;
    } else {
        arowh = g_h16 + (size_t)(off + m0 + rclampA) * KDIM + acolA;
    }
    uint32_t adst_base = AhA + (uint32_t)((arowA * SA + acolA) * 2);

    float acc[4][4][4];
    #pragma unroll
    for (int i = 0; i < 4; i++)
        #pragma unroll
        for (int j = 0; j < 4; j++)
            #pragma unroll
            for (int q = 0; q < 4; q++) acc[i][j][q] = 0.f;

    float4 pa0, pa1;                      // MODE 0 A reg pipeline
    if (MODE == 0) {
        pa0 = *(const float4*)(arowf);
        pa1 = *(const float4*)(arowf + 4);
    }

    auto stageB = [&](int c) {
        uint32_t d = bdst_base + (uint32_t)((c % NSTG) * BBUF * 2);
        const __half* s = bsrc + c * KC;
        cpasync16(d,      s);
        cpasync16(d + 16, s + 8);
    };
    auto stageA = [&](int c) {
        uint32_t d = adst_base + (uint32_t)((c % NSTG) * ABUF * 2);
        if (MODE == 1) {
            cpasync16(d, arowh + c * KC);
        } else {
            uint2 h0 = half4(pa0), h1 = half4(pa1);
            *(uint4*)((char*)smbuf + (d - smem_u32(smbuf))) = make_uint4(h0.x, h0.y, h1.x, h1.y);
            if (c + 1 < NC) {
                pa0 = *(const float4*)(arowf + (c+1)*KC);
                pa1 = *(const float4*)(arowf + (c+1)*KC + 4);
            }
        }
    };

    stageB(0); stageA(0); CP_COMMIT();
    stageB(1); stageA(1); CP_COMMIT();
    stageB(2); stageA(2); CP_COMMIT();

    for (int ch = 0; ch < NC; ch++) {
        if (ch + 2 < NC)      { CP_WAIT(2); }
        else if (ch + 1 < NC) { CP_WAIT(1); }
        else                  { CP_WAIT(0); }
        __syncthreads();
        if (ch + 3 < NC) { stageB(ch + 3); stageA(ch + 3); CP_COMMIT(); }

        int s = ch % NSTG;
        uint32_t bbA = (uint32_t)(s * ABUF * 2);
        uint32_t bbB = (uint32_t)(s * BBUF * 2);
        #pragma unroll
        for (int ks = 0; ks < 2; ks++) {
            int kb = ks * 16;
            uint32_t bH[4][2];
            #pragma unroll
            for (int p = 0; p < 2; p++) {
                uint32_t boffB = bbB + (uint32_t)(((b_row + p*16) * SA + kb + b_koff) * 2);
                ldmx4(bH[2*p][0], bH[2*p][1], bH[2*p+1][0], bH[2*p+1][1], BhA + boffB);
            }
            #pragma unroll
            for (int fi = 0; fi < 4; fi++) {
                uint32_t aoff = bbA + (uint32_t)(((a_row + fi*16) * SA + kb + a_koff) * 2);
                uint32_t aH[4];
                ldmx4(aH[0], aH[1], aH[2], aH[3], AhA + aoff);
                #pragma unroll
                for (int nj = 0; nj < 4; nj++) mma16816(acc[fi][nj], aH, bH[nj]);
            }
        }
    }

    // ---------------- epilogue ----------------
    #pragma unroll
    for (int fi = 0; fi < 4; fi++) {
        #pragma unroll
        for (int half = 0; half < 2; half++) {
            int rr = wm*64 + fi*16 + quad + half*8;
            if (rr >= cntRem) continue;
            int pos = off + m0 + rr;
            if (MODE == 0) {
                __half* dst = g_h16 + (size_t)pos * NDIM + n0;
                const float* bp = bias + (size_t)e * NDIM + n0;
                #pragma unroll
                for (int nj = 0; nj < 4; nj++) {
                    int col = wn*32 + nj*8 + tq*2;
                    float x0 = acc[fi][nj][half*2+0] + bp[col];
                    float x1 = acc[fi][nj][half*2+1] + bp[col+1];
                    float g0 = 0.5f * x0 * (1.0f + erff(x0 * 0.70710678118654752f));
                    float g1 = 0.5f * x1 * (1.0f + erff(x1 * 0.70710678118654752f));
                    __half2 o = __floats2half2_rn(g0, g1);
                    *(uint32_t*)(dst + col) = *reinterpret_cast<uint32_t*>(&o);
                }
            } else {
                int   tok = g_tok[pos];
                float p   = g_prob[pos];
                float* dst = outp + (size_t)tok * NDIM + n0;
                const float* bp = bias + (size_t)e * NDIM + n0;
                #pragma unroll
                for (int nj = 0; nj < 4; nj++) {
                    int col = wn*32 + nj*8 + tq*2;
                    atomicAdd(dst + col,     p * (acc[fi][nj][half*2+0] + bp[col]));
                    atomicAdd(dst + col + 1, p * (acc[fi][nj][half*2+1] + bp[col+1]));
                }
            }
        }
    }
}

// ---------------- launch ------------------------------------------------------
extern "C" void kernel_launch(void* const* d_in, const int* in_sizes, int n_in,
                              void* d_out, int out_size) {
    const float* z  = (const float*)d_in[0];
    const float* rw = (const float*)d_in[1];
    const float* rb = (const float*)d_in[2];
    const float* w1 = (const float*)d_in[3];
    const float* b1 = (const float*)d_in[4];
    const float* w2 = (const float*)d_in[5];
    const float* b2 = (const float*)d_in[6];
    float* out = (float*)d_out;

    cudaFuncSetAttribute(moe_gemm<DIM, HID, 0>,
                         cudaFuncAttributeMaxDynamicSharedMemorySize, SMEM_BYTES);
    cudaFuncSetAttribute(moe_gemm<HID, OUTD, 1>,
                         cudaFuncAttributeMaxDynamicSharedMemorySize, SMEM_BYTES);

    init_kernel<<<1, 32>>>();
    router_conv_kernel<<<N_TOK + CONV1_BLOCKS, 128>>>(z, rw, rb, w1);
    scatter_kernel<<<(N_TOK + 255) / 256, 256>>>();
    cudaMemsetAsync(out, 0, (size_t)N_TOK * OUTD * sizeof(float), 0);

    __half* w16_base = nullptr;
    cudaGetSymbolAddress((void**)&w16_base, g_w16);

    // gemm1: z in [0,NEXP) compute, z == NEXP converts w2 in the tail wave
    dim3 g1(HID / 256, (NPAIR + 127) / 128, NEXP + 1);
    moe_gemm<DIM, HID, 0><<<g1, 512, SMEM_BYTES>>>(z, w16_base, b1, nullptr, w2);
    dim3 g2(OUTD / 256, (NPAIR + 127) / 128, NEXP);
    moe_gemm<HID, OUTD, 1><<<g2, 512, SMEM_BYTES>>>(nullptr, w16_base + W1ELEMS, b2, out, nullptr);
}